// round 1
// baseline (speedup 1.0000x reference)
#include <cuda_runtime.h>
#include <math.h>

#define EPSV 1e-5f

// ---------------- scratch (device globals; no allocation allowed) ----------------
__device__ float g_bufA[32*3*256*256];
__device__ float g_bufB[32*3*256*256];
__device__ float g_tmp1[32*3*252*252];
__device__ float g_tmp2[32*3*252*252];
__device__ float g_stats[12*96*2];
__device__ float g_AB[96*2];
__device__ float g_lin[768];
__device__ float g_noiseA[3*32*32];
__device__ float g_noiseB[3*64*64];
__device__ float g_q[32*3*1024];
__device__ float g_k[32*3*1024];
__device__ float g_v[32*3*1024];
__device__ float g_Wv[32*3*1024];
__device__ float g_M[32*1024];

// ---------------- small kernels ----------------
__global__ void k_clear() {
    int i = blockIdx.x*blockDim.x + threadIdx.x;
    if (i < 12*96*2) g_stats[i] = 0.f;
}

__global__ void k_linear(const float* __restrict__ z, const float* __restrict__ W,
                         const float* __restrict__ b) {
    int o = blockIdx.x*blockDim.x + threadIdx.x;
    if (o >= 768) return;
    float acc = __ldg(b+o);
    const float* w = W + o*512;
    for (int j = 0; j < 512; j++) acc = fmaf(__ldg(z+j), __ldg(w+j), acc);
    g_lin[o] = acc;
}

// ---------------- conv helpers ----------------
// Pack weights of both convs into smem: layout [cin][kh][kw][8] :
// slots 0..2 = conv1 out-ch 0..2, slots 3..5 = conv2 out-ch 0..2, 6..7 pad.
__device__ __forceinline__ void load_weights(const float* w1, const float* w2, float* sw8) {
    for (int j = threadIdx.x; j < 600; j += blockDim.x) {
        int slot = j & 7, pos = j >> 3;   // pos = cin*25 + kh*5 + kw (contiguous in OIHW slice)
        float v = 0.f;
        if (slot < 3)      v = __ldg(w1 + slot*75 + pos);
        else if (slot < 6) v = __ldg(w2 + (slot-3)*75 + pos);
        sw8[j] = v;
    }
}

__device__ __forceinline__ void stats_reduce(float s0, float s1, float s2,
                                             float q0, float q1, float q2,
                                             float* stats, int n) {
    #pragma unroll
    for (int off = 16; off; off >>= 1) {
        s0 += __shfl_down_sync(0xffffffffu, s0, off);
        s1 += __shfl_down_sync(0xffffffffu, s1, off);
        s2 += __shfl_down_sync(0xffffffffu, s2, off);
        q0 += __shfl_down_sync(0xffffffffu, q0, off);
        q1 += __shfl_down_sync(0xffffffffu, q1, off);
        q2 += __shfl_down_sync(0xffffffffu, q2, off);
    }
    __shared__ float rb[8][6];
    int warp = threadIdx.x >> 5, lane = threadIdx.x & 31;
    if (lane == 0) {
        rb[warp][0]=s0; rb[warp][1]=s1; rb[warp][2]=s2;
        rb[warp][3]=q0; rb[warp][4]=q1; rb[warp][5]=q2;
    }
    __syncthreads();
    if (threadIdx.x == 0) {
        float a[6] = {0,0,0,0,0,0};
        int nw = blockDim.x >> 5;
        for (int wi = 0; wi < nw; wi++)
            for (int t = 0; t < 6; t++) a[t] += rb[wi][t];
        #pragma unroll
        for (int c = 0; c < 3; c++) {
            atomicAdd(&stats[(n*3+c)*2+0], a[c]);
            atomicAdd(&stats[(n*3+c)*2+1], a[3+c]);
        }
    }
}

// Upsample path (r > Hc): compute both convs at source res (Hc x Hc) into g_tmp1/g_tmp2,
// accumulate multiplicity-weighted stats (stats over the upsampled tensor).
__global__ void k_conv_up(const float* __restrict__ in,
                          const float* __restrict__ w1, const float* __restrict__ b1,
                          const float* __restrict__ w2, const float* __restrict__ b2,
                          float* stats, int Hin, int Hc, int r) {
    __shared__ float sw8[600];
    load_weights(w1, w2, sw8);
    __syncthreads();
    int n = blockIdx.y;
    int Wstrips = (Hc + 3) >> 2;
    int sid = blockIdx.x*blockDim.x + threadIdx.x;
    float s0=0,s1=0,s2=0,qq0=0,qq1=0,qq2=0;
    if (sid < Hc*Wstrips) {
        int sh  = sid / Wstrips;
        int sw0 = (sid - sh*Wstrips) * 4;
        float acc[6][4];
        #pragma unroll
        for (int f = 0; f < 6; f++) {
            float bb = (f < 3) ? __ldg(b1+f) : __ldg(b2+f-3);
            #pragma unroll
            for (int p = 0; p < 4; p++) acc[f][p] = bb;
        }
        #pragma unroll
        for (int ci = 0; ci < 3; ci++) {
            #pragma unroll
            for (int kh = 0; kh < 5; kh++) {
                const float* row = in + ((long)(n*3+ci)*Hin + (sh+kh))*Hin + sw0;
                float xv[8];
                #pragma unroll
                for (int j = 0; j < 8; j++)
                    xv[j] = (sw0 + j < Hin) ? __ldg(row + j) : 0.f;
                const float* wr = sw8 + (ci*25 + kh*5)*8;
                #pragma unroll
                for (int kw = 0; kw < 5; kw++) {
                    float4 wa = *(const float4*)(wr + kw*8);
                    float2 wb = *(const float2*)(wr + kw*8 + 4);
                    #pragma unroll
                    for (int p = 0; p < 4; p++) {
                        float xx = xv[p+kw];
                        acc[0][p] = fmaf(wa.x, xx, acc[0][p]);
                        acc[1][p] = fmaf(wa.y, xx, acc[1][p]);
                        acc[2][p] = fmaf(wa.z, xx, acc[2][p]);
                        acc[3][p] = fmaf(wa.w, xx, acc[3][p]);
                        acc[4][p] = fmaf(wb.x, xx, acc[4][p]);
                        acc[5][p] = fmaf(wb.y, xx, acc[5][p]);
                    }
                }
            }
        }
        int pv = min(4, Hc - sw0);
        // nearest-upsample row multiplicity: ceil((s+1)*r/Hc) - ceil(s*r/Hc)
        float wrow = (float)((((sh+1)*r + Hc - 1)/Hc) - ((sh*r + Hc - 1)/Hc));
        int chs = Hc*Hc;
        long base = ((long)(n*3)*Hc + sh)*Hc + sw0;
        for (int p = 0; p < pv; p++) {
            int swp = sw0 + p;
            float wcol = (float)((((swp+1)*r + Hc - 1)/Hc) - ((swp*r + Hc - 1)/Hc));
            float wgt = wrow * wcol;
            float y0 = acc[0][p], y1 = acc[1][p], y2 = acc[2][p];
            g_tmp1[base + p]         = y0;
            g_tmp1[base + chs + p]   = y1;
            g_tmp1[base + 2*chs + p] = y2;
            g_tmp2[base + p]         = acc[3][p];
            g_tmp2[base + chs + p]   = acc[4][p];
            g_tmp2[base + 2*chs + p] = acc[5][p];
            s0 += wgt*y0; qq0 += wgt*y0*y0;
            s1 += wgt*y1; qq1 += wgt*y1*y1;
            s2 += wgt*y2; qq2 += wgt*y2*y2;
        }
    }
    stats_reduce(s0, s1, s2, qq0, qq1, qq2, stats, n);
}

// Direct path (r <= Hc): compute convs only at the gathered (sampled) positions,
// store at r x r resolution, plain stats.
__global__ void k_conv_direct(const float* __restrict__ in,
                              const float* __restrict__ w1, const float* __restrict__ b1,
                              const float* __restrict__ w2, const float* __restrict__ b2,
                              float* stats, int Hin, int Hc, int r) {
    __shared__ float sw8[600];
    load_weights(w1, w2, sw8);
    __syncthreads();
    int n = blockIdx.y;
    int pix = blockIdx.x*blockDim.x + threadIdx.x;
    float s0=0,s1=0,s2=0,qq0=0,qq1=0,qq2=0;
    if (pix < r*r) {
        int h = pix / r, w = pix - h*r;
        int sh = (h*Hc)/r, sw = (w*Hc)/r;
        float acc[6];
        #pragma unroll
        for (int f = 0; f < 6; f++)
            acc[f] = (f < 3) ? __ldg(b1+f) : __ldg(b2+f-3);
        #pragma unroll
        for (int ci = 0; ci < 3; ci++) {
            #pragma unroll
            for (int kh = 0; kh < 5; kh++) {
                const float* row = in + ((long)(n*3+ci)*Hin + (sh+kh))*Hin + sw;
                float xv[5];
                #pragma unroll
                for (int j = 0; j < 5; j++) xv[j] = __ldg(row + j);
                const float* wr = sw8 + (ci*25 + kh*5)*8;
                #pragma unroll
                for (int kw = 0; kw < 5; kw++) {
                    float4 wa = *(const float4*)(wr + kw*8);
                    float2 wb = *(const float2*)(wr + kw*8 + 4);
                    float xx = xv[kw];
                    acc[0] = fmaf(wa.x, xx, acc[0]);
                    acc[1] = fmaf(wa.y, xx, acc[1]);
                    acc[2] = fmaf(wa.z, xx, acc[2]);
                    acc[3] = fmaf(wa.w, xx, acc[3]);
                    acc[4] = fmaf(wb.x, xx, acc[4]);
                    acc[5] = fmaf(wb.y, xx, acc[5]);
                }
            }
        }
        int rs = r*r;
        long base = (long)(n*3)*rs + pix;
        g_tmp1[base]        = acc[0];
        g_tmp1[base + rs]   = acc[1];
        g_tmp1[base + 2*rs] = acc[2];
        g_tmp2[base]        = acc[3];
        g_tmp2[base + rs]   = acc[4];
        g_tmp2[base + 2*rs] = acc[5];
        s0 = acc[0]; qq0 = acc[0]*acc[0];
        s1 = acc[1]; qq1 = acc[1]*acc[1];
        s2 = acc[2]; qq2 = acc[2]*acc[2];
    }
    stats_reduce(s0, s1, s2, qq0, qq1, qq2, stats, n);
}

// Collapse instance+batch norm mix to per-(n,c) affine: out = A*y + B (+ p2*yb later)
__global__ void k_finalize(const float* __restrict__ stats,
                           const float* __restrict__ ip, const float* __restrict__ lp,
                           const float* __restrict__ bp, const float* __restrict__ bnw,
                           const float* __restrict__ bnb, const float* __restrict__ p1p,
                           int N, float cnt) {
    __shared__ float bs[3], bq[3];
    int tid = threadIdx.x;
    if (tid < 3) { bs[tid] = 0.f; bq[tid] = 0.f; }
    __syncthreads();
    bool act = tid < N*3;
    int c = tid % 3;
    float sum = 0.f, sq = 0.f;
    if (act) {
        sum = stats[tid*2]; sq = stats[tid*2+1];
        atomicAdd(&bs[c], sum); atomicAdd(&bq[c], sq);
    }
    __syncthreads();
    if (act) {
        float mI = sum/cnt, vI = sq/cnt - mI*mI;
        float rI = rsqrtf(vI + EPSV);
        float cb = cnt * (float)N;
        float mB = bs[c]/cb, vB = bq[c]/cb - mB*mB;
        float rB = rsqrtf(vB + EPSV);
        float alpha = __ldg(ip)+__ldg(ip+1)+__ldg(ip+2)+__ldg(lp)+__ldg(lp+1)+__ldg(lp+2);
        float beta  = __ldg(bp)+__ldg(bp+1)+__ldg(bp+2);
        float bw = __ldg(bnw+c), bb2 = __ldg(bnb+c), P1 = __ldg(p1p);
        float A = P1*(1.f + alpha*rI + beta*rB*bw);
        float B = P1*(beta*(bb2 - mB*rB*bw) - alpha*mI*rI);
        g_AB[tid*2]   = A;
        g_AB[tid*2+1] = B;
    }
}

// Apply: gather (nearest upsample if S < r; identity if S == r), affine + p2*yb,
// optional noise add (broadcast over batch), optional tanh.
__global__ void k_apply(float* __restrict__ out, const float* __restrict__ p2p,
                        const float* __restrict__ noise, int N, int r, int S, int do_tanh) {
    int idx = blockIdx.x*blockDim.x + threadIdx.x;
    int total = N*3*r*r;
    if (idx >= total) return;
    int w = idx % r; int t = idx / r; int h = t % r; int nc = t / r;
    int sh = (h*S)/r, sw = (w*S)/r;
    long sidx = ((long)nc*S + sh)*S + sw;
    float A = g_AB[nc*2], B = g_AB[nc*2+1];
    float val = fmaf(g_tmp1[sidx], A, B) + __ldg(p2p)*g_tmp2[sidx];
    if (noise) { int cc = nc % 3; val += __ldg(&noise[((long)cc*r + h)*r + w]); }
    if (do_tanh) val = tanhf(val);
    out[idx] = val;
}

// ---------------- attention (softmax over output axis n) ----------------
__global__ void k_qkv(const float* __restrict__ x,
                      const float* __restrict__ qw, const float* __restrict__ qb,
                      const float* __restrict__ kw_, const float* __restrict__ kb,
                      const float* __restrict__ vw, const float* __restrict__ vb,
                      int N, int HW) {
    int idx = blockIdx.x*blockDim.x + threadIdx.x;
    if (idx >= N*HW) return;
    int b = idx / HW, pix = idx - b*HW;
    const float* xb = x + (long)b*3*HW + pix;
    float x0 = xb[0], x1 = xb[HW], x2 = xb[2*HW];
    long ob = (long)b*3*HW + pix;
    #pragma unroll
    for (int o = 0; o < 3; o++) {
        g_q[ob+o*HW] = fmaf(__ldg(qw+o*3), x0, fmaf(__ldg(qw+o*3+1), x1,
                       fmaf(__ldg(qw+o*3+2), x2, __ldg(qb+o))));
        g_k[ob+o*HW] = fmaf(__ldg(kw_+o*3), x0, fmaf(__ldg(kw_+o*3+1), x1,
                       fmaf(__ldg(kw_+o*3+2), x2, __ldg(kb+o))));
        g_v[ob+o*HW] = fmaf(__ldg(vw+o*3), x0, fmaf(__ldg(vw+o*3+1), x1,
                       fmaf(__ldg(vw+o*3+2), x2, __ldg(vb+o))));
    }
}

// pass 1: per row m, M[m] = max_n s(m,n), Z[m]; write Wv[c,m] = v[c,m]/Z[m]
__global__ void k_att1(int HW) {
    __shared__ float sq[3*1024];
    int b = blockIdx.y;
    long qb = (long)b*3*HW;
    for (int j = threadIdx.x; j < 3*HW; j += blockDim.x) sq[j] = g_q[qb+j];
    __syncthreads();
    int m = blockIdx.x*blockDim.x + threadIdx.x;
    if (m >= HW) return;
    float k0 = g_k[qb+m], k1 = g_k[qb+HW+m], k2 = g_k[qb+2*HW+m];
    float mx = -1e30f;
    for (int nn = 0; nn < HW; nn++) {
        float s = fmaf(k0, sq[nn], fmaf(k1, sq[HW+nn], k2*sq[2*HW+nn]));
        mx = fmaxf(mx, s);
    }
    float Z = 0.f;
    for (int nn = 0; nn < HW; nn++) {
        float s = fmaf(k0, sq[nn], fmaf(k1, sq[HW+nn], k2*sq[2*HW+nn]));
        Z += __expf(s - mx);
    }
    float iz = 1.f/Z;
    g_M[b*HW+m] = mx;
    g_Wv[qb+m]       = g_v[qb+m]*iz;
    g_Wv[qb+HW+m]    = g_v[qb+HW+m]*iz;
    g_Wv[qb+2*HW+m]  = g_v[qb+2*HW+m]*iz;
}

// pass 2: out[c,n] = sum_m Wv[c,m]*exp(s(m,n)-M[m]) ; in-place residual add
__global__ void k_att2(float* __restrict__ xb, int HW) {
    __shared__ float sk[3*1024];
    __shared__ float sW[3*1024];
    __shared__ float sM[1024];
    int b = blockIdx.y;
    long ob = (long)b*3*HW;
    for (int j = threadIdx.x; j < 3*HW; j += blockDim.x) { sk[j] = g_k[ob+j]; sW[j] = g_Wv[ob+j]; }
    for (int j = threadIdx.x; j < HW; j += blockDim.x) sM[j] = g_M[b*HW+j];
    __syncthreads();
    int nn = blockIdx.x*blockDim.x + threadIdx.x;
    if (nn >= HW) return;
    float q0 = g_q[ob+nn], q1 = g_q[ob+HW+nn], q2 = g_q[ob+2*HW+nn];
    float a0 = 0.f, a1 = 0.f, a2 = 0.f;
    for (int m = 0; m < HW; m++) {
        float s = fmaf(sk[m], q0, fmaf(sk[HW+m], q1, sk[2*HW+m]*q2));
        float e = __expf(s - sM[m]);
        a0 = fmaf(sW[m],      e, a0);
        a1 = fmaf(sW[HW+m],   e, a1);
        a2 = fmaf(sW[2*HW+m], e, a2);
    }
    xb[ob+nn]        += a0;
    xb[ob+HW+nn]     += a1;
    xb[ob+2*HW+nn]   += a2;
}

// ---------------- host orchestration ----------------
extern "C" void kernel_launch(void* const* d_in, const int* in_sizes, int n_in,
                              void* d_out, int out_size) {
    const float* x    = (const float*)d_in[0];
    const float* z    = (const float*)d_in[1];
    const float* linw = (const float*)d_in[2];
    const float* linb = (const float*)d_in[3];
    const float* cw   = (const float*)d_in[4];
    const float* cb   = (const float*)d_in[5];
    const float* c2w  = (const float*)d_in[6];
    const float* c2b  = (const float*)d_in[7];
    const float* qw   = (const float*)d_in[8];
    const float* qb   = (const float*)d_in[9];
    const float* kw   = (const float*)d_in[10];
    const float* kb   = (const float*)d_in[11];
    const float* vw   = (const float*)d_in[12];
    const float* vb   = (const float*)d_in[13];
    const float* inp  = (const float*)d_in[14];
    const float* lnp  = (const float*)d_in[15];
    const float* bnp  = (const float*)d_in[16];
    const float* bnw  = (const float*)d_in[17];
    const float* bnb  = (const float*)d_in[18];
    const float* p1   = (const float*)d_in[19];
    const float* p2   = (const float*)d_in[20];

    float *bufA, *bufB, *lin, *noiseA, *noiseB, *stats;
    cudaGetSymbolAddress((void**)&bufA,   g_bufA);
    cudaGetSymbolAddress((void**)&bufB,   g_bufB);
    cudaGetSymbolAddress((void**)&lin,    g_lin);
    cudaGetSymbolAddress((void**)&noiseA, g_noiseA);
    cudaGetSymbolAddress((void**)&noiseB, g_noiseB);
    cudaGetSymbolAddress((void**)&stats,  g_stats);

    k_clear<<<(12*96*2 + 255)/256, 256>>>();
    k_linear<<<3, 256>>>(z, linw, linb);

    static const int RESr[12]  = {32,64,256,128,64,32,16,16,32,64,128,256};
    static const int ATTNf[12] = {0,0,0,0,0,1,1,1,1,0,0,0};

    auto run_block = [&](int i, const float* in_ptr, float* out_ptr, int N, int Hin,
                         const float* noise, int dotanh) {
        int Hc = Hin - 4, r = RESr[i];
        float* st = stats + i*192;
        if (r > Hc) {
            int Wstrips = (Hc + 3)/4;
            dim3 g((Hc*Wstrips + 255)/256, N);
            k_conv_up<<<g, 256>>>(in_ptr, cw+i*225, cb+i*3, c2w+i*225, c2b+i*3, st, Hin, Hc, r);
        } else {
            dim3 g((r*r + 255)/256, N);
            k_conv_direct<<<g, 256>>>(in_ptr, cw+i*225, cb+i*3, c2w+i*225, c2b+i*3, st, Hin, Hc, r);
        }
        k_finalize<<<1, 96>>>(st, inp+3*i, lnp+3*i, bnp+3*i, bnw+3*i, bnb+3*i, p1+i,
                              N, (float)(r*r));
        int total = N*3*r*r;
        int S = (r > Hc) ? Hc : r;
        k_apply<<<(total + 255)/256, 256>>>(out_ptr, p2+i, noise, N, r, S, dotanh);
        if (ATTNf[i]) {
            int HW = r*r;
            k_qkv<<<(N*HW + 255)/256, 256>>>(out_ptr, qw+9*i, qb+3*i, kw+9*i, kb+3*i,
                                             vw+9*i, vb+3*i, N, HW);
            dim3 ga((HW + 255)/256, N);
            k_att1<<<ga, 256>>>(HW);
            k_att2<<<ga, 256>>>(out_ptr, HW);
        }
    };

    // noise path: Linear -> (1,3,16,16) -> block0 (->32) -> block1 (->64)
    run_block(0, lin, noiseA, 1, 16, nullptr, 0);
    run_block(1, noiseA, noiseB, 1, 32, nullptr, 0);

    // main path
    const float* cur = x;
    float* pp[2] = {bufA, bufB};
    int which = 0;
    int Hin = 256;
    for (int i = 2; i < 12; i++) {
        float* outp = (i == 11) ? (float*)d_out : pp[which];
        run_block(i, cur, outp, 32, Hin, (i == 4) ? noiseB : nullptr, (i == 11) ? 1 : 0);
        cur = outp;
        which ^= 1;
        Hin = RESr[i];
    }
}